// round 1
// baseline (speedup 1.0000x reference)
#include <cuda_runtime.h>
#include <math.h>

// Problem constants
#define B_   16
#define H_   128
#define W_   128
#define C_   256
#define CA_  128
#define RH_  16
#define RW_  16
#define NTOK 256          // RH_*RW_ tokens per batch
#define TOT_TOK (B_*NTOK) // 4096

// Scratch (device globals; no allocation allowed)
__device__ float g_xs[TOT_TOK * C_];     // downsampled tokens    [4096][256]  4MB
__device__ float g_q [TOT_TOK * CA_];    // [4096][128] 2MB
__device__ float g_k [TOT_TOK * CA_];
__device__ float g_v [TOT_TOK * CA_];
__device__ float g_o [TOT_TOK * CA_];    // attn output          2MB
__device__ float g_ow[TOT_TOK * C_];     // o @ Wo * mult        4MB

// ---------------------------------------------------------------------------
// Kernel 1: bilinear downsample 128x128 -> 16x16 (half-pixel centers)
// out pixel (i,j) = 0.25 * sum of x[8i+3..8i+4][8j+3..8j+4]
// grid 4096 blocks (one per token), 256 threads (one per channel)
// ---------------------------------------------------------------------------
__global__ void k_down(const float* __restrict__ x) {
    int token = blockIdx.x;                // b*256 + i*16 + j
    int b = token >> 8;
    int ij = token & 255;
    int i = ij >> 4, j = ij & 15;
    int c = threadIdx.x;
    const float* base = x + ((((size_t)b * H_ + (8*i+3)) * W_) + (8*j+3)) * C_;
    // row stride = W_*C_ = 32768 floats, col stride = 256 floats
    float v = base[c] + base[C_ + c] + base[W_*C_ + c] + base[W_*C_ + C_ + c];
    g_xs[(size_t)token * C_ + c] = 0.25f * v;
}

// ---------------------------------------------------------------------------
// Kernel 2: QKV projections.  A = g_xs (4096 x 256), W* = (256 x 128) row-major
// SGEMM: BM=64 BN=64 BK=16, 256 threads, 4x4 register tile.
// grid (64, 6): blockIdx.y -> {Wq:0,1  Wk:2,3  Wv:4,5}, col half = (y&1)*64
// ---------------------------------------------------------------------------
__global__ void k_qkv(const float* __restrict__ Wq,
                      const float* __restrict__ Wk,
                      const float* __restrict__ Wv) {
    int bm = blockIdx.x, bn = blockIdx.y;
    int wi = bn >> 1;
    int coloff = (bn & 1) * 64;
    const float* Bmat = (wi == 0 ? Wq : (wi == 1 ? Wk : Wv));
    float* Cout = (wi == 0 ? g_q : (wi == 1 ? g_k : g_v));

    const float* A = g_xs + (size_t)bm * 64 * C_;   // lda = 256

    __shared__ float As[16][68];   // padded: transposed A tile
    __shared__ float Bs[16][64];

    int tid = threadIdx.x;
    int tx = tid & 15, ty = tid >> 4;
    int arow = tid >> 2, ak = (tid & 3) * 4;
    int brow = tid >> 4, bcol = (tid & 15) * 4;

    float acc[4][4] = {};

    for (int k0 = 0; k0 < C_; k0 += 16) {
        float4 av = *(const float4*)(A + (size_t)arow * C_ + k0 + ak);
        As[ak+0][arow] = av.x; As[ak+1][arow] = av.y;
        As[ak+2][arow] = av.z; As[ak+3][arow] = av.w;
        float4 bv = *(const float4*)(Bmat + (size_t)(k0 + brow) * CA_ + coloff + bcol);
        *(float4*)&Bs[brow][bcol] = bv;
        __syncthreads();
#pragma unroll
        for (int kk = 0; kk < 16; ++kk) {
            float4 b4 = *(const float4*)&Bs[kk][tx*4];
            float a0 = As[kk][ty*4+0], a1 = As[kk][ty*4+1];
            float a2 = As[kk][ty*4+2], a3 = As[kk][ty*4+3];
            acc[0][0] += a0*b4.x; acc[0][1] += a0*b4.y; acc[0][2] += a0*b4.z; acc[0][3] += a0*b4.w;
            acc[1][0] += a1*b4.x; acc[1][1] += a1*b4.y; acc[1][2] += a1*b4.z; acc[1][3] += a1*b4.w;
            acc[2][0] += a2*b4.x; acc[2][1] += a2*b4.y; acc[2][2] += a2*b4.z; acc[2][3] += a2*b4.w;
            acc[3][0] += a3*b4.x; acc[3][1] += a3*b4.y; acc[3][2] += a3*b4.z; acc[3][3] += a3*b4.w;
        }
        __syncthreads();
    }
#pragma unroll
    for (int i = 0; i < 4; ++i) {
        float4 r = make_float4(acc[i][0], acc[i][1], acc[i][2], acc[i][3]);
        *(float4*)&Cout[(size_t)(bm*64 + ty*4 + i) * CA_ + coloff + tx*4] = r;
    }
}

// ---------------------------------------------------------------------------
// Kernel 3: attention.  One block per (batch, 32-query tile): 128 blocks, 256 thr.
// scores = q@k^T (no scale), softmax over keys, @v.
// Dynamic smem: Qs[32][128] | KsT[128][68] (shared with V[64][128]) | S[32][257]
// ---------------------------------------------------------------------------
__global__ void k_attn() {
    extern __shared__ float smem[];
    float* Qs  = smem;                    // 32*128 = 4096
    float* KsT = smem + 4096;             // 128*68 = 8704 (also V buffer 64*128)
    float* S   = smem + 4096 + 8704;      // 32*257 = 8224

    int b  = blockIdx.x >> 3;
    int qt = blockIdx.x & 7;
    const float* qg = g_q + (size_t)(b * NTOK + qt * 32) * CA_;
    const float* kg = g_k + (size_t)b * NTOK * CA_;
    const float* vg = g_v + (size_t)b * NTOK * CA_;

    int tid = threadIdx.x;
    int tx = tid & 15, ty = tid >> 4;

    // load Q tile (contiguous)
    for (int i = tid; i < 32 * 32; i += 256)
        ((float4*)Qs)[i] = ((const float4*)qg)[i];

    // --- scores: 4 chunks of 64 keys, K stored transposed [d][key] ---
    int lkey = tid & 63;
    int ld0  = (tid >> 6) * 32;
    for (int kc = 0; kc < 4; ++kc) {
        __syncthreads();
        const float* ksrc = kg + (size_t)(kc*64 + lkey) * CA_ + ld0;
#pragma unroll
        for (int u = 0; u < 8; ++u) {
            float4 kv = *(const float4*)(ksrc + 4*u);
            int d = ld0 + 4*u;
            KsT[(d+0)*68 + lkey] = kv.x;
            KsT[(d+1)*68 + lkey] = kv.y;
            KsT[(d+2)*68 + lkey] = kv.z;
            KsT[(d+3)*68 + lkey] = kv.w;
        }
        __syncthreads();
        float acc[2][4] = {};
        const float* q0 = &Qs[(ty*2+0) * CA_];
        const float* q1 = &Qs[(ty*2+1) * CA_];
#pragma unroll 4
        for (int d = 0; d < CA_; ++d) {
            float a0 = q0[d], a1 = q1[d];
            float4 bv = *(const float4*)&KsT[d*68 + tx*4];
            acc[0][0] += a0*bv.x; acc[0][1] += a0*bv.y; acc[0][2] += a0*bv.z; acc[0][3] += a0*bv.w;
            acc[1][0] += a1*bv.x; acc[1][1] += a1*bv.y; acc[1][2] += a1*bv.z; acc[1][3] += a1*bv.w;
        }
#pragma unroll
        for (int i = 0; i < 2; ++i)
#pragma unroll
            for (int j = 0; j < 4; ++j)
                S[(ty*2+i)*257 + kc*64 + tx*4 + j] = acc[i][j];
    }
    __syncthreads();

    // --- softmax: row = tid/8, 8 lanes per row, 32 strided cols each ---
    {
        int row = tid >> 3, sub = tid & 7;
        float* srow = &S[row * 257];
        float m = -1e30f;
#pragma unroll
        for (int i = 0; i < 32; ++i) m = fmaxf(m, srow[sub + 8*i]);
        m = fmaxf(m, __shfl_xor_sync(0xffffffffu, m, 4, 8));
        m = fmaxf(m, __shfl_xor_sync(0xffffffffu, m, 2, 8));
        m = fmaxf(m, __shfl_xor_sync(0xffffffffu, m, 1, 8));
        float sum = 0.f;
#pragma unroll
        for (int i = 0; i < 32; ++i) {
            float e = __expf(srow[sub + 8*i] - m);
            srow[sub + 8*i] = e;
            sum += e;
        }
        sum += __shfl_xor_sync(0xffffffffu, sum, 4, 8);
        sum += __shfl_xor_sync(0xffffffffu, sum, 2, 8);
        sum += __shfl_xor_sync(0xffffffffu, sum, 1, 8);
        float inv = 1.0f / sum;
#pragma unroll
        for (int i = 0; i < 32; ++i) srow[sub + 8*i] *= inv;
    }

    // --- O = P @ V : stream V in 64-key chunks (reuse KsT buffer) ---
    float oacc[2][8] = {};
    float* Vb = KsT;
    for (int vc = 0; vc < 4; ++vc) {
        __syncthreads();
        for (int i = tid; i < 64 * 32; i += 256)
            ((float4*)Vb)[i] = ((const float4*)(vg + (size_t)vc*64*CA_))[i];
        __syncthreads();
#pragma unroll 4
        for (int kk = 0; kk < 64; ++kk) {
            int key = vc*64 + kk;
            float a0 = S[(ty*2+0)*257 + key];
            float a1 = S[(ty*2+1)*257 + key];
            float4 v0 = *(const float4*)&Vb[kk*CA_ + tx*8];
            float4 v1 = *(const float4*)&Vb[kk*CA_ + tx*8 + 4];
            oacc[0][0] += a0*v0.x; oacc[0][1] += a0*v0.y; oacc[0][2] += a0*v0.z; oacc[0][3] += a0*v0.w;
            oacc[0][4] += a0*v1.x; oacc[0][5] += a0*v1.y; oacc[0][6] += a0*v1.z; oacc[0][7] += a0*v1.w;
            oacc[1][0] += a1*v0.x; oacc[1][1] += a1*v0.y; oacc[1][2] += a1*v0.z; oacc[1][3] += a1*v0.w;
            oacc[1][4] += a1*v1.x; oacc[1][5] += a1*v1.y; oacc[1][6] += a1*v1.z; oacc[1][7] += a1*v1.w;
        }
    }
#pragma unroll
    for (int i = 0; i < 2; ++i) {
        size_t row = (size_t)(b*NTOK + qt*32 + ty*2 + i);
        *(float4*)&g_o[row*CA_ + tx*8]     = make_float4(oacc[i][0], oacc[i][1], oacc[i][2], oacc[i][3]);
        *(float4*)&g_o[row*CA_ + tx*8 + 4] = make_float4(oacc[i][4], oacc[i][5], oacc[i][6], oacc[i][7]);
    }
}

// ---------------------------------------------------------------------------
// Kernel 4: g_ow = (g_o @ Wo) * mult.  A (4096x128), Wo (128x256), grid (64,4)
// ---------------------------------------------------------------------------
__global__ void k_out(const float* __restrict__ Wo, const float* __restrict__ gw) {
    int bm = blockIdx.x, bn = blockIdx.y;
    const float* A = g_o + (size_t)bm * 64 * CA_;     // lda = 128

    __shared__ float As[16][68];
    __shared__ float Bs[16][64];

    int tid = threadIdx.x;
    int tx = tid & 15, ty = tid >> 4;
    int arow = tid >> 2, ak = (tid & 3) * 4;
    int brow = tid >> 4, bcol = (tid & 15) * 4;

    float acc[4][4] = {};

    for (int k0 = 0; k0 < CA_; k0 += 16) {
        float4 av = *(const float4*)(A + (size_t)arow * CA_ + k0 + ak);
        As[ak+0][arow] = av.x; As[ak+1][arow] = av.y;
        As[ak+2][arow] = av.z; As[ak+3][arow] = av.w;
        float4 bv = *(const float4*)(Wo + (size_t)(k0 + brow) * C_ + bn*64 + bcol);
        *(float4*)&Bs[brow][bcol] = bv;
        __syncthreads();
#pragma unroll
        for (int kk = 0; kk < 16; ++kk) {
            float4 b4 = *(const float4*)&Bs[kk][tx*4];
            float a0 = As[kk][ty*4+0], a1 = As[kk][ty*4+1];
            float a2 = As[kk][ty*4+2], a3 = As[kk][ty*4+3];
            acc[0][0] += a0*b4.x; acc[0][1] += a0*b4.y; acc[0][2] += a0*b4.z; acc[0][3] += a0*b4.w;
            acc[1][0] += a1*b4.x; acc[1][1] += a1*b4.y; acc[1][2] += a1*b4.z; acc[1][3] += a1*b4.w;
            acc[2][0] += a2*b4.x; acc[2][1] += a2*b4.y; acc[2][2] += a2*b4.z; acc[2][3] += a2*b4.w;
            acc[3][0] += a3*b4.x; acc[3][1] += a3*b4.y; acc[3][2] += a3*b4.z; acc[3][3] += a3*b4.w;
        }
        __syncthreads();
    }
    int col = bn*64 + tx*4;
    float m0 = 0.5f * tanhf(4.0f * gw[col+0] + 2.5f);
    float m1 = 0.5f * tanhf(4.0f * gw[col+1] + 2.5f);
    float m2 = 0.5f * tanhf(4.0f * gw[col+2] + 2.5f);
    float m3 = 0.5f * tanhf(4.0f * gw[col+3] + 2.5f);
#pragma unroll
    for (int i = 0; i < 4; ++i) {
        float4 r = make_float4(acc[i][0]*m0, acc[i][1]*m1, acc[i][2]*m2, acc[i][3]*m3);
        *(float4*)&g_ow[(size_t)(bm*64 + ty*4 + i) * C_ + col] = r;
    }
}

// ---------------------------------------------------------------------------
// Kernel 5: bilinear upsample 16x16 -> 128x128 on g_ow, write final output.
// One float4 (4 channels) per thread. 16,777,216 threads.
// ---------------------------------------------------------------------------
__global__ void k_up(float* __restrict__ out) {
    unsigned int idx = blockIdx.x * 256u + threadIdx.x;
    int c4 = idx & 63;
    int w  = (idx >> 6) & 127;
    int h  = (idx >> 13) & 127;
    int b  = idx >> 20;

    float yy = h * 0.125f - 0.4375f;
    float y0f = floorf(yy);
    float fy = yy - y0f;
    int y0 = (int)y0f;
    int y1 = y0 + 1;
    y0 = max(y0, 0); y1 = min(y1, 15);

    float xx = w * 0.125f - 0.4375f;
    float x0f = floorf(xx);
    float fx = xx - x0f;
    int x0 = (int)x0f;
    int x1 = x0 + 1;
    x0 = max(x0, 0); x1 = min(x1, 15);

    const float* src = g_ow + (size_t)b * NTOK * C_;
    const float4* s00 = (const float4*)(src + (size_t)(y0*16 + x0) * C_) + c4;
    const float4* s01 = (const float4*)(src + (size_t)(y0*16 + x1) * C_) + c4;
    const float4* s10 = (const float4*)(src + (size_t)(y1*16 + x0) * C_) + c4;
    const float4* s11 = (const float4*)(src + (size_t)(y1*16 + x1) * C_) + c4;
    float4 a = *s00, bb = *s01, c = *s10, d = *s11;

    float w00 = (1.f-fy)*(1.f-fx), w01 = (1.f-fy)*fx, w10 = fy*(1.f-fx), w11 = fy*fx;
    float4 r;
    r.x = w00*a.x + w01*bb.x + w10*c.x + w11*d.x;
    r.y = w00*a.y + w01*bb.y + w10*c.y + w11*d.y;
    r.z = w00*a.z + w01*bb.z + w10*c.z + w11*d.z;
    r.w = w00*a.w + w01*bb.w + w10*c.w + w11*d.w;
    ((float4*)out)[idx] = r;
}

// ---------------------------------------------------------------------------
extern "C" void kernel_launch(void* const* d_in, const int* in_sizes, int n_in,
                              void* d_out, int out_size) {
    const float* x  = (const float*)d_in[0];
    const float* Wq = (const float*)d_in[1];
    const float* Wk = (const float*)d_in[2];
    const float* Wv = (const float*)d_in[3];
    const float* Wo = (const float*)d_in[4];
    const float* gw = (const float*)d_in[5];
    float* out = (float*)d_out;

    static bool attr_set = false;
    if (!attr_set) {
        cudaFuncSetAttribute(k_attn, cudaFuncAttributeMaxDynamicSharedMemorySize, 84096);
        attr_set = true;
    }

    k_down<<<TOT_TOK, 256>>>(x);
    k_qkv<<<dim3(64, 6), 256>>>(Wq, Wk, Wv);
    k_attn<<<128, 256, 84096>>>();
    k_out<<<dim3(64, 4), 256>>>(Wo, gw);
    k_up<<<(B_*H_*W_*C_/4) / 256, 256>>>(out);
}

// round 4
// speedup vs baseline: 1.1762x; 1.1762x over previous
#include <cuda_runtime.h>
#include <math.h>

#define B_   16
#define H_   128
#define W_   128
#define C_   256
#define CA_  128
#define NTOK 256
#define TOT_TOK (B_*NTOK)

__device__ float g_xs[TOT_TOK * C_];
__device__ float g_q [TOT_TOK * CA_];
__device__ float g_k [TOT_TOK * CA_];
__device__ float g_v [TOT_TOK * CA_];
__device__ float g_o [TOT_TOK * CA_];
__device__ float g_ow[TOT_TOK * C_];

// ---- packed fp32x2 helpers (Blackwell) ------------------------------------
__device__ __forceinline__ unsigned long long fma2(unsigned long long a,
                                                   unsigned long long b,
                                                   unsigned long long c) {
    unsigned long long d;
    asm("fma.rn.f32x2 %0, %1, %2, %3;" : "=l"(d) : "l"(a), "l"(b), "l"(c));
    return d;
}
__device__ __forceinline__ unsigned long long dup2(float x) {
    unsigned long long r;
    asm("mov.b64 %0, {%1, %1};" : "=l"(r) : "f"(x));
    return r;
}
__device__ __forceinline__ float2 upk(unsigned long long v) {
    float2 f;
    asm("mov.b64 {%0, %1}, %2;" : "=f"(f.x), "=f"(f.y) : "l"(v));
    return f;
}

// ---------------------------------------------------------------------------
// Kernel 1: bilinear downsample 128x128 -> 16x16
// ---------------------------------------------------------------------------
__global__ void k_down(const float* __restrict__ x) {
    int token = blockIdx.x;
    int b = token >> 8;
    int ij = token & 255;
    int i = ij >> 4, j = ij & 15;
    int c = threadIdx.x;
    const float* base = x + ((((size_t)b * H_ + (8*i+3)) * W_) + (8*j+3)) * C_;
    float v = base[c] + base[C_ + c] + base[W_*C_ + c] + base[W_*C_ + C_ + c];
    g_xs[(size_t)token * C_ + c] = 0.25f * v;
}

// ---------------------------------------------------------------------------
// Kernel 2: QKV projections (unchanged from round 1)
// ---------------------------------------------------------------------------
__global__ void k_qkv(const float* __restrict__ Wq,
                      const float* __restrict__ Wk,
                      const float* __restrict__ Wv) {
    int bm = blockIdx.x, bn = blockIdx.y;
    int wi = bn >> 1;
    int coloff = (bn & 1) * 64;
    const float* Bmat = (wi == 0 ? Wq : (wi == 1 ? Wk : Wv));
    float* Cout = (wi == 0 ? g_q : (wi == 1 ? g_k : g_v));

    const float* A = g_xs + (size_t)bm * 64 * C_;

    __shared__ float As[16][68];
    __shared__ float Bs[16][64];

    int tid = threadIdx.x;
    int tx = tid & 15, ty = tid >> 4;
    int arow = tid >> 2, ak = (tid & 3) * 4;
    int brow = tid >> 4, bcol = (tid & 15) * 4;

    float acc[4][4] = {};

    for (int k0 = 0; k0 < C_; k0 += 16) {
        float4 av = *(const float4*)(A + (size_t)arow * C_ + k0 + ak);
        As[ak+0][arow] = av.x; As[ak+1][arow] = av.y;
        As[ak+2][arow] = av.z; As[ak+3][arow] = av.w;
        float4 bv = *(const float4*)(Bmat + (size_t)(k0 + brow) * CA_ + coloff + bcol);
        *(float4*)&Bs[brow][bcol] = bv;
        __syncthreads();
#pragma unroll
        for (int kk = 0; kk < 16; ++kk) {
            float4 b4 = *(const float4*)&Bs[kk][tx*4];
            float a0 = As[kk][ty*4+0], a1 = As[kk][ty*4+1];
            float a2 = As[kk][ty*4+2], a3 = As[kk][ty*4+3];
            acc[0][0] += a0*b4.x; acc[0][1] += a0*b4.y; acc[0][2] += a0*b4.z; acc[0][3] += a0*b4.w;
            acc[1][0] += a1*b4.x; acc[1][1] += a1*b4.y; acc[1][2] += a1*b4.z; acc[1][3] += a1*b4.w;
            acc[2][0] += a2*b4.x; acc[2][1] += a2*b4.y; acc[2][2] += a2*b4.z; acc[2][3] += a2*b4.w;
            acc[3][0] += a3*b4.x; acc[3][1] += a3*b4.y; acc[3][2] += a3*b4.z; acc[3][3] += a3*b4.w;
        }
        __syncthreads();
    }
#pragma unroll
    for (int i = 0; i < 4; ++i) {
        float4 r = make_float4(acc[i][0], acc[i][1], acc[i][2], acc[i][3]);
        *(float4*)&Cout[(size_t)(bm*64 + ty*4 + i) * CA_ + coloff + tx*4] = r;
    }
}

// ---------------------------------------------------------------------------
// Kernel 3: attention, f32x2 register tiling.
// Block = (batch, 32-query tile). 256 threads, 128 blocks.
// smem: Qs[32][132] | KV[128][132] (K then V chunks) | S[32][264]
// ---------------------------------------------------------------------------
#define QP 132          // pitch for Q/K/V rows (floats)
#define SP 264          // pitch for score rows

__global__ void k_attn() {
    extern __shared__ float smem[];
    float* Qs = smem;                       // 32*132  = 4224
    float* KV = smem + 32*QP;               // 128*132 = 16896
    float* S  = smem + 32*QP + 128*QP;      // 32*264  = 8448

    int b  = blockIdx.x >> 3;
    int qt = blockIdx.x & 7;
    const float* qg = g_q + (size_t)(b * NTOK + qt * 32) * CA_;
    const float* kg = g_k + (size_t)b * NTOK * CA_;
    const float* vg = g_v + (size_t)b * NTOK * CA_;

    int tid = threadIdx.x;
    int qy = tid >> 5;       // 0..7  -> queries qy*4 .. qy*4+3
    int kx = tid & 31;       // keys kx + 32*m  (m = 0..3 per 128-key chunk)

    // load Q tile
    for (int i = tid; i < 32 * 32; i += 256) {
        int r = i >> 5, c = (i & 31) * 4;
        *(float4*)&Qs[r*QP + c] = *(const float4*)(qg + r*CA_ + c);
    }

    // ---- scores: two chunks of 128 keys ----
    for (int ch = 0; ch < 2; ++ch) {
        __syncthreads();
        const float* ksrc = kg + (size_t)ch * 128 * CA_;
        for (int i = tid; i < 128 * 32; i += 256) {
            int r = i >> 5, c = (i & 31) * 4;
            *(float4*)&KV[r*QP + c] = *(const float4*)(ksrc + r*CA_ + c);
        }
        __syncthreads();

        unsigned long long acc2[4][4];
#pragma unroll
        for (int i = 0; i < 4; ++i)
#pragma unroll
            for (int m = 0; m < 4; ++m) acc2[i][m] = 0ULL;

#pragma unroll 2
        for (int d4 = 0; d4 < 32; ++d4) {
            int dof = d4 * 4;
            ulonglong2 q0 = *(const ulonglong2*)&Qs[(qy*4+0)*QP + dof];
            ulonglong2 q1 = *(const ulonglong2*)&Qs[(qy*4+1)*QP + dof];
            ulonglong2 q2 = *(const ulonglong2*)&Qs[(qy*4+2)*QP + dof];
            ulonglong2 q3 = *(const ulonglong2*)&Qs[(qy*4+3)*QP + dof];
            ulonglong2 k0 = *(const ulonglong2*)&KV[(kx     )*QP + dof];
            ulonglong2 k1 = *(const ulonglong2*)&KV[(kx + 32)*QP + dof];
            ulonglong2 k2 = *(const ulonglong2*)&KV[(kx + 64)*QP + dof];
            ulonglong2 k3 = *(const ulonglong2*)&KV[(kx + 96)*QP + dof];
#define SC(i, qv)                                            \
            acc2[i][0] = fma2(qv.x, k0.x, acc2[i][0]);       \
            acc2[i][0] = fma2(qv.y, k0.y, acc2[i][0]);       \
            acc2[i][1] = fma2(qv.x, k1.x, acc2[i][1]);       \
            acc2[i][1] = fma2(qv.y, k1.y, acc2[i][1]);       \
            acc2[i][2] = fma2(qv.x, k2.x, acc2[i][2]);       \
            acc2[i][2] = fma2(qv.y, k2.y, acc2[i][2]);       \
            acc2[i][3] = fma2(qv.x, k3.x, acc2[i][3]);       \
            acc2[i][3] = fma2(qv.y, k3.y, acc2[i][3]);
            SC(0, q0) SC(1, q1) SC(2, q2) SC(3, q3)
#undef SC
        }
#pragma unroll
        for (int i = 0; i < 4; ++i)
#pragma unroll
            for (int m = 0; m < 4; ++m) {
                float2 p = upk(acc2[i][m]);
                S[(qy*4+i)*SP + ch*128 + kx + 32*m] = p.x + p.y;
            }
    }
    __syncthreads();

    // ---- softmax over 256 keys per query row ----
    {
        int row = tid >> 3, sub = tid & 7;
        float* srow = &S[row * SP];
        float m = -1e30f;
#pragma unroll
        for (int i = 0; i < 32; ++i) m = fmaxf(m, srow[sub + 8*i]);
        m = fmaxf(m, __shfl_xor_sync(0xffffffffu, m, 4, 8));
        m = fmaxf(m, __shfl_xor_sync(0xffffffffu, m, 2, 8));
        m = fmaxf(m, __shfl_xor_sync(0xffffffffu, m, 1, 8));
        float sum = 0.f;
#pragma unroll
        for (int i = 0; i < 32; ++i) {
            float e = __expf(srow[sub + 8*i] - m);
            srow[sub + 8*i] = e;
            sum += e;
        }
        sum += __shfl_xor_sync(0xffffffffu, sum, 4, 8);
        sum += __shfl_xor_sync(0xffffffffu, sum, 2, 8);
        sum += __shfl_xor_sync(0xffffffffu, sum, 1, 8);
        float inv = 1.0f / sum;
#pragma unroll
        for (int i = 0; i < 32; ++i) srow[sub + 8*i] *= inv;
    }

    // ---- O = P @ V : two 128-key chunks, d-pairs via f32x2 ----
    int dx = tid & 31;      // d = dx*4 .. dx*4+3
    unsigned long long po[4][2];
#pragma unroll
    for (int i = 0; i < 4; ++i) { po[i][0] = 0ULL; po[i][1] = 0ULL; }

    for (int ch = 0; ch < 2; ++ch) {
        __syncthreads();
        const float* vsrc = vg + (size_t)ch * 128 * CA_;
        for (int i = tid; i < 128 * 32; i += 256) {
            int r = i >> 5, c = (i & 31) * 4;
            *(float4*)&KV[r*QP + c] = *(const float4*)(vsrc + r*CA_ + c);
        }
        __syncthreads();

#pragma unroll 4
        for (int kk = 0; kk < 128; ++kk) {
            ulonglong2 vv = *(const ulonglong2*)&KV[kk*QP + dx*4];
#pragma unroll
            for (int i = 0; i < 4; ++i) {
                unsigned long long pd = dup2(S[(qy*4+i)*SP + ch*128 + kk]);
                po[i][0] = fma2(pd, vv.x, po[i][0]);
                po[i][1] = fma2(pd, vv.y, po[i][1]);
            }
        }
    }
#pragma unroll
    for (int i = 0; i < 4; ++i) {
        float2 lo = upk(po[i][0]);
        float2 hi = upk(po[i][1]);
        size_t row = (size_t)(b*NTOK + qt*32 + qy*4 + i);
        *(float4*)&g_o[row*CA_ + dx*4] = make_float4(lo.x, lo.y, hi.x, hi.y);
    }
}

// ---------------------------------------------------------------------------
// Kernel 4: g_ow = (g_o @ Wo) * mult.  BM=32 BN=64 BK=32, grid (128,4), f32x2
// ---------------------------------------------------------------------------
__global__ void k_out(const float* __restrict__ Wo, const float* __restrict__ gw) {
    int bm = blockIdx.x, bn = blockIdx.y;
    const float* A = g_o + (size_t)bm * 32 * CA_;

    __shared__ float As[32][36];
    __shared__ float Bs[32][64];

    int tid = threadIdx.x;
    int tx = tid & 15, ty = tid >> 4;

    unsigned long long acc2[2][2] = {{0ULL,0ULL},{0ULL,0ULL}};

    for (int k0 = 0; k0 < CA_; k0 += 32) {
        int arow = tid >> 3, ak = (tid & 7) * 4;
        float4 av = *(const float4*)(A + (size_t)arow * CA_ + k0 + ak);
        As[ak+0][arow] = av.x; As[ak+1][arow] = av.y;
        As[ak+2][arow] = av.z; As[ak+3][arow] = av.w;
        for (int i = tid; i < 512; i += 256) {
            int br = i >> 4, bc = (i & 15) * 4;
            *(float4*)&Bs[br][bc] = *(const float4*)(Wo + (size_t)(k0 + br) * C_ + bn*64 + bc);
        }
        __syncthreads();
#pragma unroll
        for (int kk = 0; kk < 32; ++kk) {
            ulonglong2 bu = *(const ulonglong2*)&Bs[kk][tx*4];
            unsigned long long a0 = dup2(As[kk][ty*2+0]);
            unsigned long long a1 = dup2(As[kk][ty*2+1]);
            acc2[0][0] = fma2(a0, bu.x, acc2[0][0]);
            acc2[0][1] = fma2(a0, bu.y, acc2[0][1]);
            acc2[1][0] = fma2(a1, bu.x, acc2[1][0]);
            acc2[1][1] = fma2(a1, bu.y, acc2[1][1]);
        }
        __syncthreads();
    }
    int col = bn*64 + tx*4;
    float m0 = 0.5f * tanhf(4.0f * gw[col+0] + 2.5f);
    float m1 = 0.5f * tanhf(4.0f * gw[col+1] + 2.5f);
    float m2 = 0.5f * tanhf(4.0f * gw[col+2] + 2.5f);
    float m3 = 0.5f * tanhf(4.0f * gw[col+3] + 2.5f);
#pragma unroll
    for (int i = 0; i < 2; ++i) {
        float2 lo = upk(acc2[i][0]);
        float2 hi = upk(acc2[i][1]);
        float4 r = make_float4(lo.x*m0, lo.y*m1, hi.x*m2, hi.y*m3);
        *(float4*)&g_ow[(size_t)(bm*32 + ty*2 + i) * C_ + col] = r;
    }
}

// ---------------------------------------------------------------------------
// Kernel 5: bilinear upsample with 8-pixel horizontal reuse.
// Block = one (b, h) output row; 1024 threads: m = tid>>6 (col group), c4 = tid&63.
// ---------------------------------------------------------------------------
__global__ void k_up(float* __restrict__ out) {
    int bx = blockIdx.x;
    int h = bx & 127;
    int b = bx >> 7;
    int tid = threadIdx.x;
    int m  = tid >> 6;     // 0..15
    int c4 = tid & 63;     // channel quad

    float yy = h * 0.125f - 0.4375f;
    float y0f = floorf(yy);
    float fy = yy - y0f;
    int y0 = (int)y0f;
    int y1 = y0 + 1;
    y0 = max(y0, 0); y1 = min(y1, 15);

    int cL = max(m - 1, 0);
    int cR = min(m + 1, 15);

    const float* src = g_ow + (size_t)b * NTOK * C_;
    float4 aL = *((const float4*)(src + (size_t)(y0*16 + cL) * C_) + c4);
    float4 aM = *((const float4*)(src + (size_t)(y0*16 + m ) * C_) + c4);
    float4 aR = *((const float4*)(src + (size_t)(y0*16 + cR) * C_) + c4);
    float4 bL = *((const float4*)(src + (size_t)(y1*16 + cL) * C_) + c4);
    float4 bM = *((const float4*)(src + (size_t)(y1*16 + m ) * C_) + c4);
    float4 bR = *((const float4*)(src + (size_t)(y1*16 + cR) * C_) + c4);

    float w0 = 1.f - fy;
    float4 vL, vM, vR;
    vL.x = w0*aL.x + fy*bL.x; vL.y = w0*aL.y + fy*bL.y; vL.z = w0*aL.z + fy*bL.z; vL.w = w0*aL.w + fy*bL.w;
    vM.x = w0*aM.x + fy*bM.x; vM.y = w0*aM.y + fy*bM.y; vM.z = w0*aM.z + fy*bM.z; vM.w = w0*aM.w + fy*bM.w;
    vR.x = w0*aR.x + fy*bR.x; vR.y = w0*aR.y + fy*bR.y; vR.z = w0*aR.z + fy*bR.z; vR.w = w0*aR.w + fy*bR.w;

    float4* obase = (float4*)out + ((size_t)(b*H_ + h) * W_ + m*8) * (C_/4) + c4;
#pragma unroll
    for (int t = 0; t < 8; ++t) {
        float fx, ax, bx2;
        float4 p, q, r;
        if (t < 4) { fx = 0.5625f + t * 0.125f; p = vL; q = vM; }
        else       { fx = t * 0.125f - 0.4375f; p = vM; q = vR; }
        ax = 1.f - fx; bx2 = fx;
        r.x = ax*p.x + bx2*q.x;
        r.y = ax*p.y + bx2*q.y;
        r.z = ax*p.z + bx2*q.z;
        r.w = ax*p.w + bx2*q.w;
        obase[(size_t)t * (C_/4)] = r;
    }
}

// ---------------------------------------------------------------------------
extern "C" void kernel_launch(void* const* d_in, const int* in_sizes, int n_in,
                              void* d_out, int out_size) {
    const float* x  = (const float*)d_in[0];
    const float* Wq = (const float*)d_in[1];
    const float* Wk = (const float*)d_in[2];
    const float* Wv = (const float*)d_in[3];
    const float* Wo = (const float*)d_in[4];
    const float* gw = (const float*)d_in[5];
    float* out = (float*)d_out;

    static bool attr_set = false;
    if (!attr_set) {
        cudaFuncSetAttribute(k_attn, cudaFuncAttributeMaxDynamicSharedMemorySize, 118272);
        attr_set = true;
    }

    k_down<<<TOT_TOK, 256>>>(x);
    k_qkv<<<dim3(64, 6), 256>>>(Wq, Wk, Wv);
    k_attn<<<128, 256, 118272>>>();
    k_out<<<dim3(128, 4), 256>>>(Wo, gw);
    k_up<<<B_*H_, 1024>>>(out);
}